// round 9
// baseline (speedup 1.0000x reference)
#include <cuda_runtime.h>
#include <cuda_fp16.h>
#include <math.h>

#define NN 100000
#define EE 1600000
#define NCAND 10000
#define GG 1000
#define ND 32
#define ED 8
#define LL 4

#define NBLK 444
#define NTHR 512
#define NT (NBLK * NTHR)
#define NWARP (NBLK * (NTHR / 32))
#define NSCAN 391            // ceil(NN/256) blocks do local scans

__device__ float g_h[NN * ND];                          // 12.8 MB
__device__ __align__(16) __half g_hs[2][NN * ED];       // double-buffered
__device__ __align__(16) __half g_hd[2][NN * ED];       // double-buffered
__device__ __align__(16) __half g_e[(size_t)EE * ED];   // 25.6 MB (dst-sorted)
__device__ int   g_srcs[EE];                            // src per sorted edge
__device__ int   g_cnt[NN];
__device__ int   g_off[NN + 1];
__device__ int   g_run[NN];
__device__ int   g_bsum[512];
__device__ float g_nl[NN];
__device__ unsigned g_mxu[GG];
__device__ float g_sum[GG];

// ---------------- grid barrier (with nanosleep backoff) ----------------
__device__ unsigned g_bcnt;
__device__ unsigned g_bgen;

__device__ __forceinline__ void gbar() {
    __syncthreads();
    if (threadIdx.x == 0) {
        __threadfence();
        unsigned gen = atomicAdd(&g_bgen, 0u);
        __threadfence();
        unsigned t = atomicAdd(&g_bcnt, 1u);
        if (t == NBLK - 1) {
            *(volatile unsigned*)&g_bcnt = 0u;
            __threadfence();
            atomicAdd(&g_bgen, 1u);
        } else {
            while (*(volatile unsigned*)&g_bgen == gen) { __nanosleep(64); }
        }
        __threadfence();
    }
    __syncthreads();
}

__device__ __forceinline__ unsigned enc_f(float f) {
    unsigned u = __float_as_uint(f);
    return (u & 0x80000000u) ? ~u : (u | 0x80000000u);
}
__device__ __forceinline__ float dec_f(unsigned k) {
    return __uint_as_float((k & 0x80000000u) ? (k ^ 0x80000000u) : ~k);
}

#define I_A (NN * ND)          // h init
#define I_B (I_A + NN * 16)    // hs/hd layer-0 fold
#define I_C (I_B + NN)         // zero cnt
#define I_D (I_C + GG)         // mx
#define I_E (I_D + GG)         // sum
#define ITOT I_E

__device__ __forceinline__ void init_phase(int gtid, float* SM,
        const float* x, const float* Wn, const float* bn,
        const float* Wel, const float* bel) {
    float* sC = SM;
    float* sc0 = SM + 32;
    int tid = threadIdx.x;
    if (tid < 48) {
        int r = tid >> 4, j = tid & 15;
        float acc = 0.f;
        if (r < 2) {
            for (int i = 0; i < ND; i++) {
                float w = (j < 8) ? Wel[i * ED + j] : Wel[(ND + i) * ED + (j - 8)];
                acc = fmaf(Wn[r * ND + i], w, acc);
            }
            sC[r * 16 + j] = acc;
        } else {
            for (int i = 0; i < ND; i++) {
                float w = (j < 8) ? Wel[i * ED + j] : Wel[(ND + i) * ED + (j - 8)];
                acc = fmaf(bn[i], w, acc);
            }
            sc0[j] = acc + ((j < 8) ? bel[j] : 0.f);
        }
    }
    __syncthreads();
    for (long t = gtid; t < ITOT; t += NT) {
        if (t < I_A) {
            int n = (int)(t >> 5), c = (int)(t & 31);
            g_h[t] = fmaf(x[2 * n], Wn[c], fmaf(x[2 * n + 1], Wn[ND + c], bn[c]));
        } else if (t < I_B) {
            long u = t - I_A;
            int n = (int)(u >> 4), j = (int)(u & 15);
            float v = fmaf(x[2 * n], sC[j], fmaf(x[2 * n + 1], sC[16 + j], sc0[j]));
            if (j < 8) g_hs[0][n * ED + j] = __float2half(v);
            else       g_hd[0][n * ED + (j - 8)] = __float2half(v);
        } else if (t < I_C) {
            g_cnt[t - I_B] = 0;
        } else if (t < I_D) {
            g_mxu[t - I_C] = 0u;
        } else {
            g_sum[t - I_D] = 0.f;
        }
    }
}

// Fused edge+node layer: warp per node over dst-sorted CSR.
// Reads hs/hd buffer rd = l&1; epilogue writes buffer 1-rd (no intra-layer race).
__device__ __forceinline__ void layer_phase(int gwarp, int lane, float* SM,
        const float* Wnl, const float* bnl, const float* Wel, const float* bel,
        const float* Wout, const float* bout, int l) {
    float* sWe = SM;          // 64 edge W
    float* sW  = SM + 64;     // 1280 node W
    float* sb  = SM + 1344;   // 32
    float* sE  = SM + 1376;   // 512
    float* sbe = SM + 1888;   // 8
    float* sWo = SM + 1896;   // 32
    float* sbo = SM + 1928;   // 1
    const int last = (l == LL - 1);
    const int rd = l & 1, wr = 1 - rd;
    if (threadIdx.x < 64)
        sWe[threadIdx.x] = Wel[l * (2 * ND + ED) * ED + 2 * ND * ED + threadIdx.x];
    for (int i = threadIdx.x; i < (ND + ED) * ND; i += NTHR)
        sW[i] = Wnl[l * (ND + ED) * ND + i];
    if (threadIdx.x < ND) sb[threadIdx.x] = bnl[l * ND + threadIdx.x];
    if (!last) {
        const float* W = Wel + (l + 1) * (2 * ND + ED) * ED;
        for (int i = threadIdx.x; i < ND * 16; i += NTHR) {
            int r = i >> 4, j = i & 15;
            sE[i] = (j < 8) ? W[r * ED + j] : W[(ND + r) * ED + (j - 8)];
        }
        if (threadIdx.x < 8) sbe[threadIdx.x] = bel[(l + 1) * ED + threadIdx.x];
    } else {
        if (threadIdx.x < ND) sWo[threadIdx.x] = Wout[threadIdx.x];
        if (threadIdx.x == 0) sbo[0] = bout[0];
    }
    __syncthreads();
    const __half* hsr = g_hs[rd];
    const __half* hdr = g_hd[rd];
    int sub = lane >> 3, col = lane & 7;
    for (int n = gwarp; n < NN; n += NWARP) {
        int beg = g_off[n], end = g_off[n + 1];
        float hdc = __half2float(hdr[n * ED + col]);
        float aggc = 0.f;
        for (int t0 = beg; t0 < end; t0 += 4) {
            int t = t0 + sub;
            bool va = (t < end);
            float ev = 0.f, hsv = 0.f;
            if (va) {
                int srcn = g_srcs[t];
                ev = __half2float(g_e[(size_t)t * ED + col]);
                hsv = __half2float(hsr[(size_t)srcn * ED + col]);
            }
            float acc = hsv + hdc;
#pragma unroll
            for (int i = 0; i < 8; i++) {
                float eiv = __shfl_sync(0xffffffffu, ev, (sub << 3) + i);
                acc = fmaf(eiv, sWe[i * ED + col], acc);
            }
            float ne = va ? fmaxf(acc, 0.f) : 0.f;
            aggc += ne;
            if (va && !last)
                g_e[(size_t)t * ED + col] = __float2half(ev + ne);
        }
        aggc += __shfl_xor_sync(0xffffffffu, aggc, 8);
        aggc += __shfl_xor_sync(0xffffffffu, aggc, 16);
        float hv = g_h[n * ND + lane];
        float r = sb[lane];
#pragma unroll
        for (int i = 0; i < ND; i++)
            r = fmaf(__shfl_sync(0xffffffffu, hv, i), sW[i * ND + lane], r);
#pragma unroll
        for (int i = 0; i < ED; i++)
            r = fmaf(__shfl_sync(0xffffffffu, aggc, i), sW[(ND + i) * ND + lane], r);
        float hnew = hv + fmaxf(r, 0.f);
        if (!last) {
            g_h[n * ND + lane] = hnew;
            float acc2 = (lane < 8) ? sbe[lane] : 0.f;
            int jj = lane & 15;
#pragma unroll
            for (int i = 0; i < ND; i++)
                acc2 = fmaf(__shfl_sync(0xffffffffu, hnew, i), sE[i * 16 + jj], acc2);
            if (lane < 8) g_hs[wr][n * ED + lane] = __float2half(acc2);
            else if (lane < 16) g_hd[wr][n * ED + (lane - 8)] = __float2half(acc2);
        } else {
            float p = hnew * sWo[lane];
#pragma unroll
            for (int s = 16; s > 0; s >>= 1)
                p += __shfl_xor_sync(0xffffffffu, p, s);
            if (lane == 0) g_nl[n] = p + sbo[0];
        }
    }
}

__global__ void __launch_bounds__(NTHR, 3)
k_mega(const float* __restrict__ x,
       const float* __restrict__ ea,
       const float* __restrict__ Wn_in, const float* __restrict__ bn_in,
       const float* __restrict__ We_in, const float* __restrict__ be_in,
       const float* __restrict__ We_l,  const float* __restrict__ be_l,
       const float* __restrict__ Wn_l,  const float* __restrict__ bn_l,
       const float* __restrict__ Wout,  const float* __restrict__ bout,
       const int* __restrict__ ei,      const int* __restrict__ batch,
       const int* __restrict__ cand,    float* __restrict__ out) {
    __shared__ float SM[2048];
    int gtid = blockIdx.x * NTHR + threadIdx.x;
    int tid = threadIdx.x;

    // 0) init (also zeroes histogram + softmax state)
    init_phase(gtid, SM, x, Wn_in, bn_in, We_l, be_l);
    gbar();

    // 1) histogram by dst
    for (int e = gtid; e < EE; e += NT)
        atomicAdd(&g_cnt[ei[EE + e]], 1);
    gbar();

    // 2) local scan (256-chunks), blocks 0..NSCAN-1
    if (blockIdx.x < NSCAN) {
        int* ssc = (int*)SM;
        int base = blockIdx.x * 256;
        int v0 = 0;
        if (tid < 256) {
            int g = base + tid;
            v0 = (g < NN) ? g_cnt[g] : 0;
            ssc[tid] = v0;
        }
        __syncthreads();
        for (int off = 1; off < 256; off <<= 1) {
            int v = 0;
            if (tid < 256 && tid >= off) v = ssc[tid - off];
            __syncthreads();
            if (tid < 256) ssc[tid] += v;
            __syncthreads();
        }
        if (tid < 256) {
            int g = base + tid;
            if (g < NN) g_off[g] = ssc[tid] - v0;
        }
        if (tid == 255) g_bsum[blockIdx.x] = ssc[255];
    }
    gbar();

    // 3) scan of block sums (block 0)
    if (blockIdx.x == 0) {
        int* ssc = (int*)SM;
        int v0 = (tid < NSCAN) ? g_bsum[tid] : 0;
        ssc[tid] = v0;
        __syncthreads();
        for (int off = 1; off < 512; off <<= 1) {
            int v = (tid >= off) ? ssc[tid - off] : 0;
            __syncthreads();
            ssc[tid] += v;
            __syncthreads();
        }
        if (tid < NSCAN) g_bsum[tid] = ssc[tid] - v0;
    }
    gbar();

    // 4) apply block offsets
    for (int i = gtid; i < NN; i += NT) {
        int v = g_off[i] + g_bsum[i >> 8];
        g_off[i] = v;
        g_run[i] = v;
    }
    if (gtid == 0) g_off[NN] = EE;
    gbar();

    // 5) scatter: sorted src + e0 row (rank-1 init folded in)
    {
        float wei[8], bei2[8];
#pragma unroll
        for (int j = 0; j < 8; j++) { wei[j] = We_in[j]; bei2[j] = be_in[j]; }
        for (int e = gtid; e < EE; e += NT) {
            int dst = ei[EE + e];
            int pos = atomicAdd(&g_run[dst], 1);
            g_srcs[pos] = ei[e];
            float v = ea[e];
            __half2 h4[4];
#pragma unroll
            for (int k = 0; k < 4; k++)
                h4[k] = __floats2half2_rn(fmaf(v, wei[2 * k], bei2[2 * k]),
                                          fmaf(v, wei[2 * k + 1], bei2[2 * k + 1]));
            ((uint4*)g_e)[pos] = *(uint4*)h4;
        }
    }
    gbar();

    // 6) layers (fused edge+node, 1 barrier each)
    int gwarp = gtid >> 5, lane = tid & 31;
    for (int l = 0; l < LL; l++) {
        layer_phase(gwarp, lane, SM, Wn_l, bn_l, We_l, be_l, Wout, bout, l);
        gbar();
    }

    // 7) readout
    for (int c = gtid; c < NCAND; c += NT) {
        int n = cand[c];
        atomicMax(&g_mxu[batch[n]], enc_f(g_nl[n]));
    }
    gbar();
    for (int c = gtid; c < NCAND; c += NT) {
        int n = cand[c];
        int s = batch[n];
        atomicAdd(&g_sum[s], expf(g_nl[n] - dec_f(g_mxu[s])));
    }
    gbar();
    for (int c = gtid; c < NCAND; c += NT) {
        int n = cand[c];
        int s = batch[n];
        out[c] = g_nl[n] - dec_f(g_mxu[s]) - logf(g_sum[s]);
    }
}

extern "C" void kernel_launch(void* const* d_in, const int* in_sizes, int n_in,
                              void* d_out, int out_size) {
    const float* x         = (const float*)d_in[0];
    const float* edge_attr = (const float*)d_in[1];
    const float* Wn_in     = (const float*)d_in[2];
    const float* bn_in     = (const float*)d_in[3];
    const float* We_in     = (const float*)d_in[4];
    const float* be_in     = (const float*)d_in[5];
    const float* We_l      = (const float*)d_in[6];
    const float* be_l      = (const float*)d_in[7];
    const float* Wn_l      = (const float*)d_in[8];
    const float* bn_l      = (const float*)d_in[9];
    const float* Wout      = (const float*)d_in[10];
    const float* bout      = (const float*)d_in[11];
    const int* edge_index  = (const int*)d_in[12];
    const int* batch       = (const int*)d_in[13];
    const int* cand        = (const int*)d_in[14];
    float* out = (float*)d_out;

    k_mega<<<NBLK, NTHR>>>(x, edge_attr, Wn_in, bn_in, We_in, be_in,
                           We_l, be_l, Wn_l, bn_l, Wout, bout,
                           edge_index, batch, cand, out);
}